// round 17
// baseline (speedup 1.0000x reference)
#include <cuda_runtime.h>
#include <cuda_fp16.h>
#include <cstdint>

// BTT dims: x (4096 x 4096), n=m=64, b=a=64, rank=8
// inner[B][n][m][r] = sum_b x[B, n*64+b] * R[n, b, m*8+r]
// out[B, m*64+a]    = sum_{n,r} inner[B][n][m][r] * L[m, n*8+r, a] + bias

#define BTOT 4096

// ---------------- scratch (device globals; no allocation allowed) ----------
__device__ __half g_xh[(size_t)BTOT * 4096];            //  32 MB  x in fp16
__device__ __half g_w1t[(size_t)64 * 512 * 64];         //   4 MB  R^T: [n][j][b], j=m*8+r
__device__ __half g_w2t[(size_t)64 * 64 * 512];         //   4 MB  L^T: [m][a][k], k=n*8+r
__device__ __half g_inner[(size_t)BTOT * 64 * 64 * 8];  // 256 MB  [B][n][m][r]

// ---------------- conversion kernels ---------------------------------------
__global__ void conv_x(const float* __restrict__ x) {
    size_t i = (size_t)blockIdx.x * 256 + threadIdx.x;
    float4 v = ((const float4*)x)[i];
    __half2 h0 = __floats2half2_rn(v.x, v.y);
    __half2 h1 = __floats2half2_rn(v.z, v.w);
    uint2 u;
    u.x = *(unsigned*)&h0;
    u.y = *(unsigned*)&h1;
    *(uint2*)(g_xh + 4 * i) = u;
}

__global__ void conv_w(const float* __restrict__ r, const float* __restrict__ l) {
    int o = blockIdx.x * 256 + threadIdx.x;   // 0..4194303
    if (o < (1 << 21)) {
        int b = o & 63, j = (o >> 6) & 511, n = o >> 15;
        g_w1t[o] = __float2half_rn(r[(size_t)(n * 64 + b) * 512 + j]);
    } else {
        int o2 = o - (1 << 21);
        int k = o2 & 511, a = (o2 >> 9) & 63, m = o2 >> 15;
        g_w2t[o2] = __float2half_rn(l[(size_t)(m * 512 + k) * 64 + a]);
    }
}

// ---------------- asm helpers ----------------------------------------------
__device__ __forceinline__ void mma16816(float* c, const unsigned* a, const unsigned* b) {
    asm volatile(
        "mma.sync.aligned.m16n8k16.row.col.f32.f16.f16.f32 "
        "{%0,%1,%2,%3}, {%4,%5,%6,%7}, {%8,%9}, {%0,%1,%2,%3};\n"
        : "+f"(c[0]), "+f"(c[1]), "+f"(c[2]), "+f"(c[3])
        : "r"(a[0]), "r"(a[1]), "r"(a[2]), "r"(a[3]), "r"(b[0]), "r"(b[1]));
}

__device__ __forceinline__ void ldsm4(unsigned& r0, unsigned& r1, unsigned& r2, unsigned& r3,
                                      unsigned addr) {
    asm volatile("ldmatrix.sync.aligned.m8n8.x4.shared.b16 {%0,%1,%2,%3}, [%4];"
                 : "=r"(r0), "=r"(r1), "=r"(r2), "=r"(r3) : "r"(addr));
}

__device__ __forceinline__ void cpa16(unsigned dst, const void* src) {
    asm volatile("cp.async.cg.shared.global [%0], [%1], 16;" :: "r"(dst), "l"(src));
}
__device__ __forceinline__ void cpcommit() { asm volatile("cp.async.commit_group;"); }
template <int N> __device__ __forceinline__ void cpwait() {
    asm volatile("cp.async.wait_group %0;" :: "n"(N));
}

// 128B-row swizzle (8 granules of 16B): g' = g ^ (row&7)
#define SWZ128(off) ((off) ^ (((off) >> 3) & 0x70))

// ---------------- pass 1: inner = X @ R (2 j-tiles per CTA) -----------------
// Grid (jh 0..1, n 0..63, bt 0..31) = 4096 CTAs. Rows are 64 halves = 128B,
// stored with SWZ128 (no padding). A at 0, B0 at 16384B, B1 at 32768B = 48KB.
#define P1_B0 16384
#define P1_B1 32768

__global__ __launch_bounds__(256, 3) void btt_pass1() {
    extern __shared__ __half dsm[];
    const int jh = blockIdx.x;
    const int n  = blockIdx.y;
    const int bt = blockIdx.z;     // 0..31, 128 rows each
    const int tid = threadIdx.x;
    const int grow0 = bt * 128;
    const int jbase = jh * 256;
    unsigned sbase = (unsigned)__cvta_generic_to_shared(dsm);

    // group0 = A + B(tile0); group1 = B(tile1)
#pragma unroll
    for (int i = 0; i < 4; i++) {
        int q = tid + i * 256;          // 0..1023
        int row = q >> 3, c8 = q & 7;   // 128 rows x 8 x 16B
        unsigned off = SWZ128(row * 128 + c8 * 16);
        cpa16(sbase + off, g_xh + (size_t)(grow0 + row) * 4096 + n * 64 + c8 * 8);
        cpa16(sbase + P1_B0 + off, g_w1t + (size_t)(n * 512 + jbase + row) * 64 + c8 * 8);
    }
    cpcommit();
#pragma unroll
    for (int i = 0; i < 4; i++) {
        int q = tid + i * 256;
        int row = q >> 3, c8 = q & 7;
        unsigned off = SWZ128(row * 128 + c8 * 16);
        cpa16(sbase + P1_B1 + off, g_w1t + (size_t)(n * 512 + jbase + 128 + row) * 64 + c8 * 8);
    }
    cpcommit();

    const int warp = tid >> 5, lane = tid & 31;
    const int wm = warp >> 2, wn = warp & 3;   // 2 x 4 warp grid, warp tile 64x32
    const int g = lane >> 2, t = lane & 3;
    const int rl = lane & 7, sel = lane >> 3;
    const int rowlA = rl + (sel & 1) * 8, gselA = sel >> 1;       // A frag lane row/granule
    const int rowlB = (sel >> 1) * 8 + rl, gselB = sel & 1;       // B frag lane row/granule

#pragma unroll
    for (int half = 0; half < 2; half++) {
        if (half == 0) cpwait<1>(); else cpwait<0>();
        __syncthreads();

        float acc[4][4][4];
#pragma unroll
        for (int mf = 0; mf < 4; mf++)
#pragma unroll
            for (int nf = 0; nf < 4; nf++)
#pragma unroll
                for (int c = 0; c < 4; c++) acc[mf][nf][c] = 0.f;

        unsigned bBase = sbase + (half == 0 ? P1_B0 : P1_B1);
#pragma unroll
        for (int ks = 0; ks < 4; ks++) {
            const int g0 = ks * 2;      // granule of k0 = ks*16 halves
            unsigned af[4][4], bf[4][2];
#pragma unroll
            for (int mf = 0; mf < 4; mf++) {
                int row = wm * 64 + mf * 16 + rowlA;
                ldsm4(af[mf][0], af[mf][1], af[mf][2], af[mf][3],
                      sbase + row * 128 + (((g0 + gselA) ^ rl) << 4));
            }
#pragma unroll
            for (int p = 0; p < 2; p++) {
                int row = wn * 32 + p * 16 + rowlB;
                ldsm4(bf[2 * p][0], bf[2 * p][1], bf[2 * p + 1][0], bf[2 * p + 1][1],
                      bBase + row * 128 + (((g0 + gselB) ^ rl) << 4));
            }
#pragma unroll
            for (int mf = 0; mf < 4; mf++)
#pragma unroll
                for (int nf = 0; nf < 4; nf++) mma16816(acc[mf][nf], af[mf], bf[nf]);
        }

        // epilogue: fp16 store to g_inner[B][n][j]  (j contiguous)
#pragma unroll
        for (int mf = 0; mf < 4; mf++) {
            int lrow = grow0 + wm * 64 + mf * 16 + g;
#pragma unroll
            for (int nf = 0; nf < 4; nf++) {
                int jg = jbase + half * 128 + wn * 32 + nf * 8 + 2 * t;
                size_t base = ((size_t)lrow * 64 + n) * 512 + jg;
                __half2 h0 = __floats2half2_rn(acc[mf][nf][0], acc[mf][nf][1]);
                *(__half2*)(g_inner + base) = h0;
                __half2 h1 = __floats2half2_rn(acc[mf][nf][2], acc[mf][nf][3]);
                *(__half2*)(g_inner + base + (size_t)8 * 64 * 512) = h1;   // row +8
            }
        }
    }
}

// ---------------- pass 2: out = inner @ L (2 m per CTA) ---------------------
// Grid (mq 0..31, bt 0..63) = 2048 CTAs. Out tile 64 rows x 128 cols (2 m).
// K=512 in 16 chunks of 32, 2-stage pipeline, one sync per chunk.
// Rows are 32 halves = 64B, swizzled: granule g' = g ^ ((row>>1)&3).
// Halves layout: A[s] at s*4096 ([mi][row][32k]); B[s] at 8192 + s*4096.
#define P2_STG 4096
#define P2_BOFF 8192

__device__ __forceinline__ void p2_load(unsigned sbase, int s, int kc, int bt, int mq, int tid) {
#pragma unroll
    for (int i = 0; i < 2; i++) {       // A: 512 x 16B
        int q = tid + i * 256;
        int row = q >> 3, nl = (q >> 1) & 3, mi = q & 1;
        unsigned dsth = s * P2_STG + mi * 2048 + row * 32 + ((nl ^ ((row >> 1) & 3)) * 8);
        cpa16(sbase + dsth * 2,
              g_inner + (((size_t)(bt * 64 + row) * 64 + kc * 4 + nl) * 64 + mq * 2 + mi) * 8);
    }
#pragma unroll
    for (int i = 0; i < 2; i++) {       // B: 512 x 16B
        int q = tid + i * 256;
        int mi = q >> 8, a = (q >> 2) & 63, kl = q & 3;
        unsigned dsth = P2_BOFF + s * P2_STG + mi * 2048 + a * 32 + ((kl ^ ((a >> 1) & 3)) * 8);
        cpa16(sbase + dsth * 2,
              g_w2t + ((size_t)(mq * 2 + mi) * 64 + a) * 512 + kc * 32 + kl * 8);
    }
    cpcommit();
}

__global__ __launch_bounds__(256, 3) void btt_pass2(const float* __restrict__ bias,
                                                    float* __restrict__ out) {
    extern __shared__ __half dsm[];
    const int mq = blockIdx.x;     // 0..31
    const int bt = blockIdx.y;     // 0..63, 64 rows each
    const int tid = threadIdx.x;
    unsigned sbase = (unsigned)__cvta_generic_to_shared(dsm);

    const int warp = tid >> 5, lane = tid & 31;
    const int wm = warp >> 2, wn = warp & 3;  // warp tile 32 rows x 32 cols
    const int mi = wn >> 1, a0 = (wn & 1) * 32;
    const int g = lane >> 2, t = lane & 3;
    const int rl = lane & 7, sel = lane >> 3;
    const int rowlA = rl + (sel & 1) * 8, gselA = sel >> 1;
    const int rowlB = (sel >> 1) * 8 + rl, gselB = sel & 1;
    const int swz = (rl >> 1) & 3;

    float acc[2][4][4];
#pragma unroll
    for (int mf = 0; mf < 2; mf++)
#pragma unroll
        for (int nf = 0; nf < 4; nf++)
#pragma unroll
            for (int c = 0; c < 4; c++) acc[mf][nf][c] = 0.f;

    p2_load(sbase, 0, 0, bt, mq, tid);

    for (int kc = 0; kc < 16; kc++) {
        const int s = kc & 1;
        cpwait<0>();        // group kc complete (issued during compute of kc-1)
        __syncthreads();    // all warps done reading stage s (prev contents)
        if (kc + 1 < 16) p2_load(sbase, s ^ 1, kc + 1, bt, mq, tid);

        unsigned aBase = sbase + (s * P2_STG + mi * 2048) * 2;
        unsigned bBase = sbase + (P2_BOFF + s * P2_STG + mi * 2048) * 2;
#pragma unroll
        for (int ks = 0; ks < 2; ks++) {
            const int g0 = ks * 2;
            unsigned af[2][4], bf[4][2];
#pragma unroll
            for (int mf = 0; mf < 2; mf++) {
                int row = wm * 32 + mf * 16 + rowlA;
                ldsm4(af[mf][0], af[mf][1], af[mf][2], af[mf][3],
                      aBase + (row * 32 + (((g0 + gselA) ^ swz) * 8)) * 2);
            }
#pragma unroll
            for (int p = 0; p < 2; p++) {
                int row = a0 + p * 16 + rowlB;
                ldsm4(bf[2 * p][0], bf[2 * p][1], bf[2 * p + 1][0], bf[2 * p + 1][1],
                      bBase + (row * 32 + (((g0 + gselB) ^ swz) * 8)) * 2);
            }
#pragma unroll
            for (int mf = 0; mf < 2; mf++)
#pragma unroll
                for (int nf = 0; nf < 4; nf++) mma16816(acc[mf][nf], af[mf], bf[nf]);
        }
    }

    // epilogue: fp32 out + bias
#pragma unroll
    for (int mf = 0; mf < 2; mf++) {
        int row = bt * 64 + wm * 32 + mf * 16 + g;
#pragma unroll
        for (int nf = 0; nf < 4; nf++) {
            int col = (mq * 2 + mi) * 64 + a0 + nf * 8 + 2 * t;
            float b0 = bias[col], b1 = bias[col + 1];
            float2 v0 = make_float2(acc[mf][nf][0] + b0, acc[mf][nf][1] + b1);
            *(float2*)(out + (size_t)row * 4096 + col) = v0;
            float2 v1 = make_float2(acc[mf][nf][2] + b0, acc[mf][nf][3] + b1);
            *(float2*)(out + (size_t)(row + 8) * 4096 + col) = v1;
        }
    }
}

// ---------------- launch ----------------------------------------------------
extern "C" void kernel_launch(void* const* d_in, const int* in_sizes, int n_in,
                              void* d_out, int out_size) {
    const float* x    = (const float*)d_in[0];  // (4,1024,4096)
    const float* rw   = (const float*)d_in[1];  // (64,64,512)
    const float* lw   = (const float*)d_in[2];  // (64,512,64)
    const float* bias = (const float*)d_in[3];  // (4096)
    float* out = (float*)d_out;

    cudaFuncSetAttribute(btt_pass1, cudaFuncAttributeMaxDynamicSharedMemorySize, 49152);
    cudaFuncSetAttribute(btt_pass2, cudaFuncAttributeMaxDynamicSharedMemorySize, 32768);

    conv_x<<<16384, 256>>>(x);
    conv_w<<<16384, 256>>>(rw, lw);
    btt_pass1<<<dim3(2, 64, 32), 256, 49152>>>();
    btt_pass2<<<dim3(32, 64), 256, 32768>>>(bias, out);
}